// round 1
// baseline (speedup 1.0000x reference)
#include <cuda_runtime.h>
#include <math_constants.h>

// DarkCLoss: y = max_c(1 - x) ; dc = 35x35 sliding max (-inf pad) ; out = -mean(|dc|)
// Decomposition: 35-tap max == 5-tap max followed by 7-tap max with dilation 5
// (clamped tap indices reproduce the -inf-padded / range-clamped window exactly).

#define BB 16
#define HH 512
#define WW 512
#define HWP (HH * WW)
#define NPIX (BB * HWP)

// Scratch (allocation-free rule: __device__ globals)
__device__ float g_v5[NPIX];         // channel-max + vertical 5-tap result
__device__ float g_part[BB * HH];    // per-(b,row) partial sums

// ---------------------------------------------------------------------------
// K1: fused channel-min + vertical 5-tap. Each thread: one (b, w) column,
// 8 consecutive output rows, streaming 12 input rows through registers.
// Reads x coalesced in w; writes v5 coalesced in w.
// ---------------------------------------------------------------------------
__global__ void k1_chanmin_vert5(const float* __restrict__ x) {
    int idx  = blockIdx.x * blockDim.x + threadIdx.x;   // BB*64*WW threads
    int w    = idx & (WW - 1);
    int t    = idx >> 9;
    int jblk = t & 63;
    int b    = t >> 6;
    int j0   = jblk << 3;                               // first output row

    const float* xb = x + (size_t)b * 3 * HWP + w;

    float g[12];
#pragma unroll
    for (int k = 0; k < 12; k++) {
        int row = j0 - 2 + k;
        if (row < 0 || row >= HH) {
            g[k] = -CUDART_INF_F;
        } else {
            const float* p = xb + row * WW;
            float v = fminf(p[0], fminf(p[HWP], p[2 * HWP]));
            g[k] = 1.0f - v;                            // max_c(1-x) = 1 - min_c(x)
        }
    }

    float* out = g_v5 + (size_t)b * HWP + (size_t)j0 * WW + w;
#pragma unroll
    for (int r = 0; r < 8; r++) {
        float m = g[r];
        m = fmaxf(m, g[r + 1]);
        m = fmaxf(m, g[r + 2]);
        m = fmaxf(m, g[r + 3]);
        m = fmaxf(m, g[r + 4]);
        out[r * WW] = m;
    }
}

// ---------------------------------------------------------------------------
// K2: one block per (b, output row h).
//  1) vertical 7-tap dilated-5 over g_v5 rows -> s_v[w]
//  2) horizontal 5-tap on s_v -> s_h5[w]
//  3) horizontal 7-tap dilated-5 on s_h5, abs, block-sum -> g_part
// All tap indices clamped to [0, 511] (== -inf padding semantics).
// ---------------------------------------------------------------------------
__global__ void k2_vert7_horiz(void) {
    __shared__ float s_v[WW];
    __shared__ float s_h5[WW];
    __shared__ float s_red[8];

    int b   = blockIdx.x >> 9;
    int h   = blockIdx.x & (HH - 1);
    int tid = threadIdx.x;                 // 256 threads, 2 w's each

    const float* vb = g_v5 + (size_t)b * HWP;

    for (int w = tid; w < WW; w += 256) {
        float m = -CUDART_INF_F;
#pragma unroll
        for (int k = -3; k <= 3; k++) {
            int row = h + 5 * k;
            row = max(0, min(HH - 1, row));
            m = fmaxf(m, vb[row * WW + w]);
        }
        s_v[w] = m;
    }
    __syncthreads();

    for (int w = tid; w < WW; w += 256) {
        float m = s_v[w];
#pragma unroll
        for (int d = -2; d <= 2; d++) {
            int ww = max(0, min(WW - 1, w + d));
            m = fmaxf(m, s_v[ww]);
        }
        s_h5[w] = m;
    }
    __syncthreads();

    float acc = 0.0f;
    for (int w = tid; w < WW; w += 256) {
        float m = -CUDART_INF_F;
#pragma unroll
        for (int k = -3; k <= 3; k++) {
            int ww = max(0, min(WW - 1, w + 5 * k));
            m = fmaxf(m, s_h5[ww]);
        }
        acc += fabsf(m);
    }

    // block reduction (deterministic: fixed order per block)
#pragma unroll
    for (int o = 16; o; o >>= 1) acc += __shfl_down_sync(0xffffffffu, acc, o);
    if ((tid & 31) == 0) s_red[tid >> 5] = acc;
    __syncthreads();
    if (tid < 8) {
        acc = s_red[tid];
#pragma unroll
        for (int o = 4; o; o >>= 1) acc += __shfl_down_sync(0xffu, acc, o, 8);
        if (tid == 0) g_part[blockIdx.x] = acc;
    }
}

// ---------------------------------------------------------------------------
// K3: deterministic final reduction of BB*HH partials in double.
// ---------------------------------------------------------------------------
__global__ void k3_final(float* __restrict__ out) {
    __shared__ double s[256];
    int tid = threadIdx.x;
    double acc = 0.0;
    for (int i = tid; i < BB * HH; i += 256) acc += (double)g_part[i];
    s[tid] = acc;
    __syncthreads();
    for (int stride = 128; stride; stride >>= 1) {
        if (tid < stride) s[tid] += s[tid + stride];
        __syncthreads();
    }
    if (tid == 0) out[0] = (float)(-s[0] / (double)NPIX);
}

// ---------------------------------------------------------------------------
extern "C" void kernel_launch(void* const* d_in, const int* in_sizes, int n_in,
                              void* d_out, int out_size) {
    const float* x = (const float*)d_in[0];
    (void)in_sizes; (void)n_in; (void)out_size;

    k1_chanmin_vert5<<<(BB * 64 * WW) / 256, 256>>>(x);
    k2_vert7_horiz<<<BB * HH, 256>>>();
    k3_final<<<1, 256>>>((float*)d_out);
}

// round 3
// speedup vs baseline: 1.0010x; 1.0010x over previous
#include <cuda_runtime.h>
#include <math_constants.h>

// DarkCLoss: y = max_c(1 - x) ; dc = 35x35 sliding max (-inf pad) ; out = -mean(|dc|)
// Decomposition: 35-tap max == 5-tap max followed by 7-tap max with dilation 5
// (clamped tap indices reproduce the -inf-padded / range-clamped window exactly).

#define BB 16
#define HH 512
#define WW 512
#define HWP (HH * WW)
#define NPIX (BB * HWP)

// Scratch (allocation-free rule: __device__ globals)
__device__ float g_v5[NPIX];         // channel-max + vertical 5-tap result
__device__ float g_part[BB * HH];    // per-(b,row) partial sums

// ---------------------------------------------------------------------------
// K1: fused channel-min + vertical 5-tap. Each thread: one (b, w) column,
// 8 consecutive output rows, streaming 12 input rows through registers.
// Reads x coalesced in w; writes v5 coalesced in w.
// ---------------------------------------------------------------------------
__global__ void k1_chanmin_vert5(const float* __restrict__ x) {
    int idx  = blockIdx.x * blockDim.x + threadIdx.x;   // BB*64*WW threads
    int w    = idx & (WW - 1);
    int t    = idx >> 9;
    int jblk = t & 63;
    int b    = t >> 6;
    int j0   = jblk << 3;                               // first output row

    const float* xb = x + (size_t)b * 3 * HWP + w;

    float g[12];
#pragma unroll
    for (int k = 0; k < 12; k++) {
        int row = j0 - 2 + k;
        if (row < 0 || row >= HH) {
            g[k] = -CUDART_INF_F;
        } else {
            const float* p = xb + row * WW;
            float v = fminf(p[0], fminf(p[HWP], p[2 * HWP]));
            g[k] = 1.0f - v;                            // max_c(1-x) = 1 - min_c(x)
        }
    }

    float* out = g_v5 + (size_t)b * HWP + (size_t)j0 * WW + w;
#pragma unroll
    for (int r = 0; r < 8; r++) {
        float m = g[r];
        m = fmaxf(m, g[r + 1]);
        m = fmaxf(m, g[r + 2]);
        m = fmaxf(m, g[r + 3]);
        m = fmaxf(m, g[r + 4]);
        out[r * WW] = m;
    }
}

// ---------------------------------------------------------------------------
// K2: one block per (b, output row h).
//  1) vertical 7-tap dilated-5 over g_v5 rows -> s_v[w]
//  2) horizontal 5-tap on s_v -> s_h5[w]
//  3) horizontal 7-tap dilated-5 on s_h5, abs, block-sum -> g_part
// All tap indices clamped to [0, 511] (== -inf padding semantics).
// ---------------------------------------------------------------------------
__global__ void k2_vert7_horiz(void) {
    __shared__ float s_v[WW];
    __shared__ float s_h5[WW];
    __shared__ float s_red[8];

    int b   = blockIdx.x >> 9;
    int h   = blockIdx.x & (HH - 1);
    int tid = threadIdx.x;                 // 256 threads, 2 w's each

    const float* vb = g_v5 + (size_t)b * HWP;

    for (int w = tid; w < WW; w += 256) {
        float m = -CUDART_INF_F;
#pragma unroll
        for (int k = -3; k <= 3; k++) {
            int row = h + 5 * k;
            row = max(0, min(HH - 1, row));
            m = fmaxf(m, vb[row * WW + w]);
        }
        s_v[w] = m;
    }
    __syncthreads();

    for (int w = tid; w < WW; w += 256) {
        float m = s_v[w];
#pragma unroll
        for (int d = -2; d <= 2; d++) {
            int ww = max(0, min(WW - 1, w + d));
            m = fmaxf(m, s_v[ww]);
        }
        s_h5[w] = m;
    }
    __syncthreads();

    float acc = 0.0f;
    for (int w = tid; w < WW; w += 256) {
        float m = -CUDART_INF_F;
#pragma unroll
        for (int k = -3; k <= 3; k++) {
            int ww = max(0, min(WW - 1, w + 5 * k));
            m = fmaxf(m, s_h5[ww]);
        }
        acc += fabsf(m);
    }

    // block reduction (deterministic: fixed order per block)
#pragma unroll
    for (int o = 16; o; o >>= 1) acc += __shfl_down_sync(0xffffffffu, acc, o);
    if ((tid & 31) == 0) s_red[tid >> 5] = acc;
    __syncthreads();
    if (tid < 8) {
        acc = s_red[tid];
#pragma unroll
        for (int o = 4; o; o >>= 1) acc += __shfl_down_sync(0xffu, acc, o, 8);
        if (tid == 0) g_part[blockIdx.x] = acc;
    }
}

// ---------------------------------------------------------------------------
// K3: deterministic final reduction of BB*HH partials in double.
// ---------------------------------------------------------------------------
__global__ void k3_final(float* __restrict__ out) {
    __shared__ double s[256];
    int tid = threadIdx.x;
    double acc = 0.0;
    for (int i = tid; i < BB * HH; i += 256) acc += (double)g_part[i];
    s[tid] = acc;
    __syncthreads();
    for (int stride = 128; stride; stride >>= 1) {
        if (tid < stride) s[tid] += s[tid + stride];
        __syncthreads();
    }
    if (tid == 0) out[0] = (float)(-s[0] / (double)NPIX);
}

// ---------------------------------------------------------------------------
extern "C" void kernel_launch(void* const* d_in, const int* in_sizes, int n_in,
                              void* d_out, int out_size) {
    const float* x = (const float*)d_in[0];
    (void)in_sizes; (void)n_in; (void)out_size;

    k1_chanmin_vert5<<<(BB * 64 * WW) / 256, 256>>>(x);
    k2_vert7_horiz<<<BB * HH, 256>>>();
    k3_final<<<1, 256>>>((float*)d_out);
}